// round 1
// baseline (speedup 1.0000x reference)
#include <cuda_runtime.h>
#include <math.h>

#define NS   1024      // sentences = B*D
#define SEQ  64
#define EDIM 256
#define HDIM 512
#define GDIM 2048      // 4*H
#define BB   32
#define DD   32

// -------- scratch (__device__ globals; no allocations allowed) --------
__device__ float g_x  [NS * SEQ * EDIM];                 // 67 MB embeddings
__device__ float g_xg [268435456];                       // 2*SEQ*NS*GDIM = 1.07 GB input-proj gates
__device__ float g_h  [2 * NS * HDIM];
__device__ float g_c  [2 * NS * HDIM];
__device__ float g_pool[2 * NS * HDIM];
__device__ int   g_len[NS];

// -------- sentence lengths --------
__global__ void k_len(const int* __restrict__ docs) {
    int n = blockIdx.x * blockDim.x + threadIdx.x;
    if (n >= NS) return;
    int cnt = 0;
    #pragma unroll
    for (int t = 0; t < SEQ; t++) cnt += (docs[n * SEQ + t] != 0);
    g_len[n] = cnt;
}

// -------- zero state + pool (must re-zero every launch: graph replay) --------
__global__ void k_zero() {
    int idx = blockIdx.x * blockDim.x + threadIdx.x;  // 2*NS*HDIM = 1048576
    g_h[idx] = 0.f; g_c[idx] = 0.f; g_pool[idx] = 0.f;
}

// -------- embedding gather (float4) --------
__global__ void k_embed(const int* __restrict__ docs, const float* __restrict__ emb) {
    int idx = blockIdx.x * blockDim.x + threadIdx.x;  // NS*SEQ*EDIM/4 = 4194304
    int q  = idx & 63;       // E/4 = 64 float4 per row
    int sp = idx >> 6;       // sentence*SEQ + t
    int tok = docs[sp];
    ((float4*)g_x)[idx] = ((const float4*)emb)[tok * 64 + q];
}

// -------- input GEMM: xg[dir][step][n][g] = x[n,time]·W_ih^T + b --------
// tile 128(M=n) x 64(N=gate), K=256, KT=16, 256 thr, 8x4 per thread
__global__ void __launch_bounds__(256) k_igemm(
    const float* __restrict__ wih_f, const float* __restrict__ b_f,
    const float* __restrict__ wih_b, const float* __restrict__ b_b)
{
    const int dir  = blockIdx.z & 1;
    const int step = blockIdx.z >> 1;
    const int time = dir ? (SEQ - 1 - step) : step;
    const int n0 = blockIdx.y * 128;
    const int g0 = blockIdx.x * 64;
    const float* __restrict__ W    = dir ? wih_b : wih_f;
    const float* __restrict__ bias = dir ? b_b   : b_f;

    __shared__ __align__(16) float As[16 * 129];
    __shared__ __align__(16) float Bs[16 * 68];

    const int tid = threadIdx.x;
    const int tx = tid & 15, ty = tid >> 4;

    float acc[8][4];
    #pragma unroll
    for (int i = 0; i < 8; i++)
        #pragma unroll
        for (int j = 0; j < 4; j++) acc[i][j] = 0.f;

    for (int k0 = 0; k0 < EDIM; k0 += 16) {
        #pragma unroll
        for (int it = 0; it < 8; it++) {      // A: 128x16
            int e = tid + it * 256;
            int m = e >> 4, kk = e & 15;
            As[kk * 129 + m] = g_x[(size_t)(n0 + m) * (SEQ * EDIM) + time * EDIM + k0 + kk];
        }
        #pragma unroll
        for (int it = 0; it < 4; it++) {      // B: 64x16
            int e = tid + it * 256;
            int c = e >> 4, kk = e & 15;
            Bs[kk * 68 + c] = W[(g0 + c) * EDIM + k0 + kk];
        }
        __syncthreads();
        #pragma unroll
        for (int kk = 0; kk < 16; kk++) {
            float a[8];
            #pragma unroll
            for (int i = 0; i < 8; i++) a[i] = As[kk * 129 + ty * 8 + i];
            float4 b4 = ((const float4*)(Bs + kk * 68))[tx];
            float b[4] = {b4.x, b4.y, b4.z, b4.w};
            #pragma unroll
            for (int i = 0; i < 8; i++)
                #pragma unroll
                for (int j = 0; j < 4; j++) acc[i][j] += a[i] * b[j];
        }
        __syncthreads();
    }

    size_t base = ((size_t)(dir * SEQ + step) * NS) * GDIM;
    float4 bv = ((const float4*)(bias + g0))[tx];
    #pragma unroll
    for (int i = 0; i < 8; i++) {
        int m = n0 + ty * 8 + i;
        float4 v = make_float4(acc[i][0] + bv.x, acc[i][1] + bv.y,
                               acc[i][2] + bv.z, acc[i][3] + bv.w);
        *(float4*)&g_xg[base + (size_t)m * GDIM + g0 + tx * 4] = v;
    }
}

// -------- one recurrent step (both dirs): g = h·W_hh^T + xg; update c,h,pool --------
// block = (h-tile j0:32, n-tile n0:64, dir). Output tile 64 x 128 (4 gate groups x 32), K=512
__global__ void __launch_bounds__(256) k_step(
    const float* __restrict__ whh_f, const float* __restrict__ whh_b, int step)
{
    const int dir = blockIdx.z;
    const int n0  = blockIdx.y * 64;
    const int j0  = blockIdx.x * 32;
    const float* __restrict__ W = dir ? whh_b : whh_f;

    __shared__ __align__(16) float As[16 * 65];
    __shared__ __align__(16) float Bs[16 * 132];
    __shared__ __align__(16) float ysh[64 * 132];

    const int tid = threadIdx.x;
    const int tx = tid & 15, ty = tid >> 4;

    float acc[4][8];
    #pragma unroll
    for (int i = 0; i < 4; i++)
        #pragma unroll
        for (int j = 0; j < 8; j++) acc[i][j] = 0.f;

    const float* __restrict__ hbase = g_h + dir * NS * HDIM;

    for (int k0 = 0; k0 < HDIM; k0 += 16) {
        #pragma unroll
        for (int it = 0; it < 4; it++) {      // A: 64x16 of h
            int e = tid + it * 256;
            int m = e >> 4, kk = e & 15;
            As[kk * 65 + m] = hbase[(n0 + m) * HDIM + k0 + kk];
        }
        #pragma unroll
        for (int it = 0; it < 8; it++) {      // B: 128x16 of W_hh (4 gate groups)
            int e = tid + it * 256;
            int c = e >> 4, kk = e & 15;
            int gate = (c >> 5) * HDIM + j0 + (c & 31);
            Bs[kk * 132 + c] = W[gate * HDIM + k0 + kk];
        }
        __syncthreads();
        #pragma unroll
        for (int kk = 0; kk < 16; kk++) {
            float a[4];
            #pragma unroll
            for (int i = 0; i < 4; i++) a[i] = As[kk * 65 + ty * 4 + i];
            float4 b0 = *(const float4*)&Bs[kk * 132 + tx * 8];
            float4 b1 = *(const float4*)&Bs[kk * 132 + tx * 8 + 4];
            float b[8] = {b0.x, b0.y, b0.z, b0.w, b1.x, b1.y, b1.z, b1.w};
            #pragma unroll
            for (int i = 0; i < 4; i++)
                #pragma unroll
                for (int j = 0; j < 8; j++) acc[i][j] += a[i] * b[j];
        }
        __syncthreads();
    }

    // add xg, stage to shared for gate exchange
    size_t xgbase = ((size_t)(dir * SEQ + step) * NS) * GDIM;
    #pragma unroll
    for (int i = 0; i < 4; i++) {
        int m = ty * 4 + i;
        const float* __restrict__ xr = &g_xg[xgbase + (size_t)(n0 + m) * GDIM];
        float v[8];
        #pragma unroll
        for (int j = 0; j < 8; j++) {
            int c = tx * 8 + j;
            int gate = (c >> 5) * HDIM + j0 + (c & 31);
            v[j] = acc[i][j] + xr[gate];
        }
        *(float4*)&ysh[m * 132 + tx * 8]     = make_float4(v[0], v[1], v[2], v[3]);
        *(float4*)&ysh[m * 132 + tx * 8 + 4] = make_float4(v[4], v[5], v[6], v[7]);
    }
    __syncthreads();

    // pointwise LSTM cell update + fused masked-mean pool accumulation
    const int u = dir ? (SEQ - 1 - step) : step;   // original time index
    float* __restrict__ cb = g_c    + dir * NS * HDIM;
    float* __restrict__ hb = g_h    + dir * NS * HDIM;
    float* __restrict__ pb = g_pool + dir * NS * HDIM;
    #pragma unroll
    for (int it = 0; it < 8; it++) {               // 64*32 items / 256 thr
        int idx = tid + it * 256;
        int m = idx >> 5, j = idx & 31;
        float yi = ysh[m * 132 + j];
        float yf = ysh[m * 132 + 32 + j];
        float yg = ysh[m * 132 + 64 + j];
        float yo = ysh[m * 132 + 96 + j];
        float si = 1.f / (1.f + expf(-yi));
        float sf = 1.f / (1.f + expf(-yf));
        float so = 1.f / (1.f + expf(-yo));
        float tg = tanhf(yg);
        int gi = (n0 + m) * HDIM + j0 + j;
        float c = sf * cb[gi] + si * tg;
        float h = so * tanhf(c);
        cb[gi] = c;
        hb[gi] = h;
        if (u < g_len[n0 + m]) pb[gi] += h;
    }
}

// -------- final: divide by length, doc mask, write output (B,D,2H) --------
__global__ void k_final(const int* __restrict__ doc_lens, float* __restrict__ out) {
    int idx = blockIdx.x * blockDim.x + threadIdx.x;  // 1048576
    int j  = idx & 1023;         // 2H
    int nd = idx >> 10;          // b*DD + d
    int b = nd >> 5, d = nd & 31;
    float v = 0.f;
    if (d < doc_lens[b]) {
        int dir = j >> 9;
        int jj  = j & 511;
        int len = g_len[nd];
        float denom = (float)(len > 0 ? len : 1);
        v = g_pool[dir * NS * HDIM + nd * HDIM + jj] / denom;
    }
    out[idx] = v;
}

extern "C" void kernel_launch(void* const* d_in, const int* in_sizes, int n_in,
                              void* d_out, int out_size)
{
    const int* docs     = (const int*)d_in[0];
    const int* doc_lens = (const int*)d_in[1];
    // max_doc_len may or may not appear as a scalar input; detect by size
    int base = (n_in >= 10 && in_sizes[2] == 1) ? 3 : 2;
    const float* emb   = (const float*)d_in[base + 0];
    const float* wih_f = (const float*)d_in[base + 1];
    const float* whh_f = (const float*)d_in[base + 2];
    const float* b_f   = (const float*)d_in[base + 3];
    const float* wih_b = (const float*)d_in[base + 4];
    const float* whh_b = (const float*)d_in[base + 5];
    const float* b_b   = (const float*)d_in[base + 6];
    float* out = (float*)d_out;

    k_len  <<<4, 256>>>(docs);
    k_zero <<<4096, 256>>>();
    k_embed<<<16384, 256>>>(docs, emb);
    k_igemm<<<dim3(GDIM / 64, NS / 128, 2 * SEQ), 256>>>(wih_f, b_f, wih_b, b_b);
    for (int t = 0; t < SEQ; t++)
        k_step<<<dim3(HDIM / 32, NS / 64, 2), 256>>>(whh_f, whh_b, t);
    k_final<<<4096, 256>>>(doc_lens, out);
}

// round 3
// speedup vs baseline: 1.9856x; 1.9856x over previous
#include <cuda_runtime.h>
#include <cuda_fp16.h>
#include <cstdint>
#include <math.h>

#define NS   1024
#define SEQ  64
#define EDIM 256
#define HDIM 512
#define GDIM 2048

// ---------------- device scratch (no allocations allowed) ----------------
__device__ float g_xg[268435456];            // [dir][t][n][p]  1.07 GB
__device__ float g_hbuf[2][2 * NS * HDIM];   // double-buffered h
__device__ float g_c   [2 * NS * HDIM];
__device__ float g_pool[2 * NS * HDIM];
__device__ int   g_len [NS];
__device__ __half g_whh_h[2 * GDIM * HDIM];  // permuted fp16 hi plane of W_hh
__device__ __half g_whh_l[2 * GDIM * HDIM];  // lo plane
__device__ __half g_wih_h[2 * GDIM * EDIM];
__device__ __half g_wih_l[2 * GDIM * EDIM];

// ---------------- helpers ----------------
__device__ __forceinline__ uint32_t smem_u32(const void* ptr) {
    uint32_t a;
    asm("{ .reg .u64 t; cvta.to.shared.u64 t, %1; cvt.u32.u64 %0, t; }" : "=r"(a) : "l"(ptr));
    return a;
}

#define STS128(r0,r1,r2,r3,addr) \
    asm volatile("st.shared.v4.b32 [%0], {%1, %2, %3, %4};" :: "r"(addr), "r"(r0), "r"(r1), "r"(r2), "r"(r3) : "memory")

#define CP_ASYNC16(dst, src) \
    asm volatile("cp.async.cg.shared.global [%0], [%1], 16;" :: "r"(dst), "l"(src) : "memory")
#define CP_COMMIT() asm volatile("cp.async.commit_group;" ::: "memory")
#define CP_WAIT(n)  asm volatile("cp.async.wait_group %0;" :: "n"(n) : "memory")

__device__ __forceinline__ void ldsm4(uint32_t* r, uint32_t addr) {
    asm volatile("ldmatrix.sync.aligned.m8n8.x4.shared.b16 {%0,%1,%2,%3}, [%4];"
        : "=r"(r[0]), "=r"(r[1]), "=r"(r[2]), "=r"(r[3]) : "r"(addr));
}

__device__ __forceinline__ void mma16816(float* c, const uint32_t* a, const uint32_t* b) {
    asm volatile("mma.sync.aligned.m16n8k16.row.col.f32.f16.f16.f32 "
        "{%0,%1,%2,%3}, {%4,%5,%6,%7}, {%8,%9}, {%0,%1,%2,%3};"
        : "+f"(c[0]), "+f"(c[1]), "+f"(c[2]), "+f"(c[3])
        : "r"(a[0]), "r"(a[1]), "r"(a[2]), "r"(a[3]), "r"(b[0]), "r"(b[1]));
}

__device__ __forceinline__ void split2(float a, float b, uint32_t& hi, uint32_t& lo) {
    __half ha = __float2half_rn(a), hb = __float2half_rn(b);
    __half la = __float2half_rn(a - __half2float(ha));
    __half lb = __float2half_rn(b - __half2float(hb));
    __half2 H = __halves2half2(ha, hb);
    __half2 L = __halves2half2(la, lb);
    hi = *reinterpret_cast<uint32_t*>(&H);
    lo = *reinterpret_cast<uint32_t*>(&L);
}

// ---------------- smem layout ----------------
// A: 2 buffers x [hi 128x80 | lo 128x80]  (2 x 20480)
// B: 3 buffers x [hi 256x80 | lo 256x80]  (3 x 40960)  at offset 40960
#define A_BUF    20480
#define A_LO     10240
#define B_BASE   40960
#define B_BUF    40960
#define B_LO     20480
#define SMEM_SZ  163840

__device__ __forceinline__ void ldga(float4* f, const float* src) {
    const float4* s = (const float4*)src;
    f[0] = s[0]; f[1] = s[1]; f[2] = s[2]; f[3] = s[3];
}

__device__ __forceinline__ void stsA(uint32_t base, const float4* f) {
    uint32_t H[8], L[8];
    split2(f[0].x, f[0].y, H[0], L[0]); split2(f[0].z, f[0].w, H[1], L[1]);
    split2(f[1].x, f[1].y, H[2], L[2]); split2(f[1].z, f[1].w, H[3], L[3]);
    split2(f[2].x, f[2].y, H[4], L[4]); split2(f[2].z, f[2].w, H[5], L[5]);
    split2(f[3].x, f[3].y, H[6], L[6]); split2(f[3].z, f[3].w, H[7], L[7]);
    STS128(H[0], H[1], H[2], H[3], base);
    STS128(H[4], H[5], H[6], H[7], base + 16);
    STS128(L[0], L[1], L[2], L[3], base + A_LO);
    STS128(L[4], L[5], L[6], L[7], base + A_LO + 16);
}

// fill one B chunk (256 rows x 32 k, hi+lo planes) via cp.async
__device__ __forceinline__ void fillB(uint32_t dstbase, const __half* sH, const __half* sL,
                                      int k0, int tid, int Kdim) {
    #pragma unroll
    for (int i = 0; i < 8; i++) {
        int s = tid + i * 256;                 // 0..2047 slots of 16B
        int plane = s >> 10, row = (s >> 2) & 255, kc = s & 3;
        const __half* sp = (plane ? sL : sH) + (size_t)row * Kdim + k0 + kc * 8;
        uint32_t dp = dstbase + plane * B_LO + row * 80 + kc * 16;
        CP_ASYNC16(dp, sp);
    }
}

// one K32 chunk of 3-pass split-fp16 mma for warp tile 64x64
__device__ __forceinline__ void compute_chunk(float C[4][8][4], uint32_t ab, uint32_t bb,
                                              uint32_t a_off, uint32_t b_off) {
    #pragma unroll
    for (int kk = 0; kk < 2; kk++) {
        uint32_t Ah[4][4], Bh[4][4];
        #pragma unroll
        for (int mf = 0; mf < 4; mf++) ldsm4(Ah[mf], ab + mf * 1280 + kk * 32 + a_off);
        #pragma unroll
        for (int nq = 0; nq < 4; nq++) ldsm4(Bh[nq], bb + nq * 1280 + kk * 32 + b_off);
        #pragma unroll
        for (int mf = 0; mf < 4; mf++)
            #pragma unroll
            for (int nf = 0; nf < 8; nf++)
                mma16816(C[mf][nf], Ah[mf], &Bh[nf >> 1][(nf & 1) * 2]);
        uint32_t Al[4][4];
        #pragma unroll
        for (int mf = 0; mf < 4; mf++) ldsm4(Al[mf], ab + A_LO + mf * 1280 + kk * 32 + a_off);
        #pragma unroll
        for (int mf = 0; mf < 4; mf++)
            #pragma unroll
            for (int nf = 0; nf < 8; nf++)
                mma16816(C[mf][nf], Al[mf], &Bh[nf >> 1][(nf & 1) * 2]);
        uint32_t Bl[4][4];
        #pragma unroll
        for (int nq = 0; nq < 4; nq++) ldsm4(Bl[nq], bb + B_LO + nq * 1280 + kk * 32 + b_off);
        #pragma unroll
        for (int mf = 0; mf < 4; mf++)
            #pragma unroll
            for (int nf = 0; nf < 8; nf++)
                mma16816(C[mf][nf], Ah[mf], &Bl[nf >> 1][(nf & 1) * 2]);
    }
}

// ---------------- small kernels ----------------
__global__ void k_len(const int* __restrict__ docs) {
    int n = blockIdx.x * blockDim.x + threadIdx.x;
    if (n >= NS) return;
    int cnt = 0;
    #pragma unroll
    for (int t = 0; t < SEQ; t++) cnt += (docs[n * SEQ + t] != 0);
    g_len[n] = cnt;
}

__global__ void k_zero() {
    int idx = blockIdx.x * blockDim.x + threadIdx.x;
    g_hbuf[0][idx] = 0.f; g_c[idx] = 0.f; g_pool[idx] = 0.f;
}

// pre-split + permute weights into fp16 hi/lo planes, row p holds W[(p&3)*H + (p>>2)]
__global__ void k_prep_hh(const float* __restrict__ wf, const float* __restrict__ wb) {
    int idx = blockIdx.x * blockDim.x + threadIdx.x;  // 524288
    int k4 = idx & 127, p = (idx >> 7) & 2047, dir = idx >> 18;
    const float* W = dir ? wb : wf;
    float4 v = *(const float4*)(W + (size_t)((p & 3) * HDIM + (p >> 2)) * HDIM + k4 * 4);
    uint32_t h0, l0, h1, l1;
    split2(v.x, v.y, h0, l0); split2(v.z, v.w, h1, l1);
    size_t off = (size_t)(dir * GDIM + p) * HDIM + k4 * 4;
    *(uint2*)(g_whh_h + off) = make_uint2(h0, h1);
    *(uint2*)(g_whh_l + off) = make_uint2(l0, l1);
}

__global__ void k_prep_ih(const float* __restrict__ wf, const float* __restrict__ wb) {
    int idx = blockIdx.x * blockDim.x + threadIdx.x;  // 262144
    int k4 = idx & 63, p = (idx >> 6) & 2047, dir = idx >> 17;
    const float* W = dir ? wb : wf;
    float4 v = *(const float4*)(W + (size_t)((p & 3) * HDIM + (p >> 2)) * EDIM + k4 * 4);
    uint32_t h0, l0, h1, l1;
    split2(v.x, v.y, h0, l0); split2(v.z, v.w, h1, l1);
    size_t off = (size_t)(dir * GDIM + p) * EDIM + k4 * 4;
    *(uint2*)(g_wih_h + off) = make_uint2(h0, h1);
    *(uint2*)(g_wih_l + off) = make_uint2(l0, l1);
}

// ---------------- input GEMM: xg = embed(docs)·W_ih'^T + b' ----------------
// CTA M=128 (rows m = n*64+t), N=256 (permuted gates), K=256; grid (8, 512, 2)
__global__ void __launch_bounds__(256, 1) k_igemm(
    const int* __restrict__ docs, const float* __restrict__ emb,
    const float* __restrict__ b_f, const float* __restrict__ b_b)
{
    extern __shared__ char smem[];
    const uint32_t sb = smem_u32(smem);
    const int tid = threadIdx.x;
    const int dir = blockIdx.z;
    const int m0  = blockIdx.y * 128;
    const int p0  = blockIdx.x * 256;
    const float* __restrict__ bias = dir ? b_b : b_f;
    const __half* __restrict__ BH = g_wih_h + (size_t)(dir * GDIM + p0) * EDIM;
    const __half* __restrict__ BL = g_wih_l + (size_t)(dir * GDIM + p0) * EDIM;

    const int arow = tid >> 1, akh = tid & 1;
    const int tok = docs[m0 + arow];
    const float* __restrict__ asrc = emb + (size_t)tok * EDIM + akh * 16;
    const uint32_t asts_off = arow * 80 + akh * 32;

    const int lane = tid & 31, w = tid >> 5;
    const int mw = w & 1, nw = w >> 1;
    const uint32_t a_off = (mw * 64 + (lane & 15)) * 80 + (lane >> 4) * 16;
    const uint32_t b_off = (nw * 64 + (lane & 7) + ((lane >> 4) << 3)) * 80 + ((lane >> 3) & 1) * 16;

    float C[4][8][4];
    #pragma unroll
    for (int a = 0; a < 4; a++)
        #pragma unroll
        for (int b = 0; b < 8; b++)
            #pragma unroll
            for (int q = 0; q < 4; q++) C[a][b][q] = 0.f;

    {
        float4 f[4]; ldga(f, asrc);
        stsA(sb + asts_off, f);
        fillB(sb + B_BASE, BH, BL, 0, tid, EDIM);
        CP_COMMIT();
    }
    int bcur = 0, bnext = 1;
    float4 fs[4];
    #pragma unroll 1
    for (int ch = 0; ch < 8; ch++) {
        if (ch + 1 < 8) {
            ldga(fs, asrc + (ch + 1) * 32);
            fillB(sb + B_BASE + bnext * B_BUF, BH, BL, (ch + 1) * 32, tid, EDIM);
            CP_COMMIT();
            CP_WAIT(1);
        } else CP_WAIT(0);
        __syncthreads();
        compute_chunk(C, sb + (ch & 1) * A_BUF, sb + B_BASE + bcur * B_BUF, a_off, b_off);
        if (ch + 1 < 8) stsA(sb + ((ch + 1) & 1) * A_BUF + asts_off, fs);
        bcur = bnext; bnext = (bnext == 2) ? 0 : bnext + 1;
    }

    // epilogue: + bias, store to xg[dir][t][n][p]
    const int qr = lane >> 2, c2 = (lane & 3) * 2;
    float bias0[8], bias1[8];
    #pragma unroll
    for (int nf = 0; nf < 8; nf++) {
        int p = p0 + nw * 64 + nf * 8 + c2;
        bias0[nf] = bias[(p & 3) * HDIM + (p >> 2)];
        bias1[nf] = bias[((p + 1) & 3) * HDIM + ((p + 1) >> 2)];
    }
    #pragma unroll
    for (int mf = 0; mf < 4; mf++) {
        #pragma unroll
        for (int rh = 0; rh < 2; rh++) {
            const int m = m0 + mw * 64 + mf * 16 + qr + rh * 8;
            const int ns = m >> 6, tt = m & 63;
            float* __restrict__ xo = g_xg + ((size_t)(dir * SEQ + tt) * NS + ns) * GDIM + p0 + nw * 64 + c2;
            #pragma unroll
            for (int nf = 0; nf < 8; nf++) {
                float2 v;
                v.x = C[mf][nf][rh * 2 + 0] + bias0[nf];
                v.y = C[mf][nf][rh * 2 + 1] + bias1[nf];
                *(float2*)(xo + nf * 8) = v;
            }
        }
    }
}

// ---------------- recurrent step ----------------
// CTA M=128 (n), N=256 (permuted gates), K=512; grid (8, 8, 2) = 128 CTAs
__global__ void __launch_bounds__(256, 1) k_step(int step)
{
    extern __shared__ char smem[];
    const uint32_t sb = smem_u32(smem);
    const int tid = threadIdx.x;
    const int dir = blockIdx.z;
    const int n0  = blockIdx.y * 128;
    const int p0  = blockIdx.x * 256;
    const int u = dir ? (SEQ - 1 - step) : step;

    const float* __restrict__ hin = g_hbuf[step & 1] + (size_t)dir * NS * HDIM;
    const __half* __restrict__ BH = g_whh_h + (size_t)(dir * GDIM + p0) * HDIM;
    const __half* __restrict__ BL = g_whh_l + (size_t)(dir * GDIM + p0) * HDIM;

    const int arow = tid >> 1, akh = tid & 1;
    const float* __restrict__ asrc = hin + (size_t)(n0 + arow) * HDIM + akh * 16;
    const uint32_t asts_off = arow * 80 + akh * 32;

    const int lane = tid & 31, w = tid >> 5;
    const int mw = w & 1, nw = w >> 1;
    const uint32_t a_off = (mw * 64 + (lane & 15)) * 80 + (lane >> 4) * 16;
    const uint32_t b_off = (nw * 64 + (lane & 7) + ((lane >> 4) << 3)) * 80 + ((lane >> 3) & 1) * 16;

    float C[4][8][4];
    #pragma unroll
    for (int a = 0; a < 4; a++)
        #pragma unroll
        for (int b = 0; b < 8; b++)
            #pragma unroll
            for (int q = 0; q < 4; q++) C[a][b][q] = 0.f;

    {
        float4 f[4]; ldga(f, asrc);
        stsA(sb + asts_off, f);
        fillB(sb + B_BASE, BH, BL, 0, tid, HDIM);
        CP_COMMIT();
    }
    int bcur = 0, bnext = 1;
    float4 fs[4];
    #pragma unroll 1
    for (int ch = 0; ch < 16; ch++) {
        if (ch + 1 < 16) {
            ldga(fs, asrc + (ch + 1) * 32);
            fillB(sb + B_BASE + bnext * B_BUF, BH, BL, (ch + 1) * 32, tid, HDIM);
            CP_COMMIT();
            CP_WAIT(1);
        } else CP_WAIT(0);
        __syncthreads();
        compute_chunk(C, sb + (ch & 1) * A_BUF, sb + B_BASE + bcur * B_BUF, a_off, b_off);
        if (ch + 1 < 16) stsA(sb + ((ch + 1) & 1) * A_BUF + asts_off, fs);
        bcur = bnext; bnext = (bnext == 2) ? 0 : bnext + 1;
    }

    // epilogue: y = C + xg; gate exchange via shfl; cell update; fused pool
    const int qr = lane >> 2, c2 = (lane & 3) * 2, odd = lane & 1;
    const float* __restrict__ xgrow = g_xg + (size_t)(dir * SEQ + u) * NS * GDIM;
    float* __restrict__ cbase = g_c    + (size_t)dir * NS * HDIM;
    float* __restrict__ pbase = g_pool + (size_t)dir * NS * HDIM;
    float* __restrict__ hout  = g_hbuf[(step + 1) & 1] + (size_t)dir * NS * HDIM;

    #pragma unroll
    for (int mf = 0; mf < 4; mf++) {
        #pragma unroll
        for (int rh = 0; rh < 2; rh++) {
            const int row = n0 + mw * 64 + mf * 16 + qr + rh * 8;
            const bool inlen = (u < g_len[row]);
            const float* __restrict__ xr = xgrow + (size_t)row * GDIM + p0 + nw * 64 + c2;
            #pragma unroll
            for (int nf = 0; nf < 8; nf++) {
                float2 xv = *(const float2*)(xr + nf * 8);
                float y0 = C[mf][nf][rh * 2 + 0] + xv.x;
                float y1 = C[mf][nf][rh * 2 + 1] + xv.y;
                float o0 = __shfl_xor_sync(0xffffffffu, y0, 1);
                float o1 = __shfl_xor_sync(0xffffffffu, y1, 1);
                if (!odd) {
                    float si = 1.f / (1.f + expf(-y0));
                    float sf = 1.f / (1.f + expf(-y1));
                    float tg = tanhf(o0);
                    float so = 1.f / (1.f + expf(-o1));
                    int j = (p0 + nw * 64 + nf * 8 + c2) >> 2;
                    int ci = row * HDIM + j;
                    float c = sf * cbase[ci] + si * tg;
                    float h = so * tanhf(c);
                    cbase[ci] = c;
                    hout[ci]  = h;
                    if (inlen) pbase[ci] += h;
                }
            }
        }
    }
}

// ---------------- final: pool/len, doc mask ----------------
__global__ void k_final(const int* __restrict__ doc_lens, float* __restrict__ out) {
    int idx = blockIdx.x * blockDim.x + threadIdx.x;  // 1048576
    int j  = idx & 1023;
    int nd = idx >> 10;
    int b = nd >> 5, d = nd & 31;
    float v = 0.f;
    if (d < doc_lens[b]) {
        int dirn = j >> 9;
        int jj   = j & 511;
        int len = g_len[nd];
        float denom = (float)(len > 0 ? len : 1);
        v = g_pool[dirn * NS * HDIM + nd * HDIM + jj] / denom;
    }
    out[idx] = v;
}

extern "C" void kernel_launch(void* const* d_in, const int* in_sizes, int n_in,
                              void* d_out, int out_size)
{
    const int* docs     = (const int*)d_in[0];
    const int* doc_lens = (const int*)d_in[1];
    int base = (n_in >= 10 && in_sizes[2] == 1) ? 3 : 2;
    const float* emb   = (const float*)d_in[base + 0];
    const float* wih_f = (const float*)d_in[base + 1];
    const float* whh_f = (const float*)d_in[base + 2];
    const float* b_f   = (const float*)d_in[base + 3];
    const float* wih_b = (const float*)d_in[base + 4];
    const float* whh_b = (const float*)d_in[base + 5];
    const float* b_b   = (const float*)d_in[base + 6];
    float* out = (float*)d_out;

    cudaFuncSetAttribute(k_igemm, cudaFuncAttributeMaxDynamicSharedMemorySize, SMEM_SZ);
    cudaFuncSetAttribute(k_step,  cudaFuncAttributeMaxDynamicSharedMemorySize, SMEM_SZ);

    k_len    <<<4, 256>>>(docs);
    k_zero   <<<4096, 256>>>();
    k_prep_ih<<<1024, 256>>>(wih_f, wih_b);
    k_prep_hh<<<2048, 256>>>(whh_f, whh_b);
    k_igemm  <<<dim3(8, 512, 2), 256, SMEM_SZ>>>(docs, emb, b_f, b_b);
    for (int t = 0; t < SEQ; t++)
        k_step<<<dim3(8, 8, 2), 256, SMEM_SZ>>>(t);
    k_final  <<<4096, 256>>>(doc_lens, out);
}

// round 4
// speedup vs baseline: 2.5616x; 1.2901x over previous
#include <cuda_runtime.h>
#include <cuda_fp16.h>
#include <cstdint>
#include <math.h>

#define NS   1024
#define SEQ  64
#define EDIM 256
#define HDIM 512
#define GDIM 2048
#define VOC  32000

// ---------------- device scratch ----------------
__device__ __half g_h16[2][2][2 * NS * HDIM];      // [parity][plane][dir*NS*H + n*H + k]
__device__ float  g_c   [2 * NS * HDIM];
__device__ float  g_pool[2 * NS * HDIM];
__device__ int    g_len [NS];
__device__ __half g_whh_h[2 * GDIM * HDIM], g_whh_l[2 * GDIM * HDIM];
__device__ __half g_wih_h[2 * GDIM * EDIM], g_wih_l[2 * GDIM * EDIM];
__device__ __half g_emb_h[VOC * EDIM],      g_emb_l[VOC * EDIM];

// ---------------- helpers ----------------
__device__ __forceinline__ uint32_t smem_u32(const void* ptr) {
    uint32_t a;
    asm("{ .reg .u64 t; cvta.to.shared.u64 t, %1; cvt.u32.u64 %0, t; }" : "=r"(a) : "l"(ptr));
    return a;
}
#define CP_ASYNC16(dst, src) \
    asm volatile("cp.async.cg.shared.global [%0], [%1], 16;" :: "r"(dst), "l"(src) : "memory")
#define CP_COMMIT() asm volatile("cp.async.commit_group;" ::: "memory")
#define CP_WAIT(n)  asm volatile("cp.async.wait_group %0;" :: "n"(n) : "memory")

__device__ __forceinline__ void ldsm4(uint32_t* r, uint32_t addr) {
    asm volatile("ldmatrix.sync.aligned.m8n8.x4.shared.b16 {%0,%1,%2,%3}, [%4];"
        : "=r"(r[0]), "=r"(r[1]), "=r"(r[2]), "=r"(r[3]) : "r"(addr));
}
__device__ __forceinline__ void mma16816(float* c, const uint32_t* a, const uint32_t* b) {
    asm volatile("mma.sync.aligned.m16n8k16.row.col.f32.f16.f16.f32 "
        "{%0,%1,%2,%3}, {%4,%5,%6,%7}, {%8,%9}, {%0,%1,%2,%3};"
        : "+f"(c[0]), "+f"(c[1]), "+f"(c[2]), "+f"(c[3])
        : "r"(a[0]), "r"(a[1]), "r"(a[2]), "r"(a[3]), "r"(b[0]), "r"(b[1]));
}
__device__ __forceinline__ void split2(float a, float b, uint32_t& hi, uint32_t& lo) {
    __half ha = __float2half_rn(a), hb = __float2half_rn(b);
    __half la = __float2half_rn(a - __half2float(ha));
    __half lb = __float2half_rn(b - __half2float(hb));
    __half2 H = __halves2half2(ha, hb);
    __half2 L = __halves2half2(la, lb);
    hi = *reinterpret_cast<uint32_t*>(&H);
    lo = *reinterpret_cast<uint32_t*>(&L);
}

// ---------------- smem layout ----------------
// stage: Ahi 128x80 | Alo 128x80 | Bhi 256x80 | Blo 256x80 = 61440 B; 3 stages
#define ST_SZ   61440
#define A_LO    10240
#define B_HI    20480
#define B_PL    20480
#define SM_TOK  184320
#define SM_BIAS 184832
#define SM_LEN  185856
#define SMEM_SZ 186368
#define NCH     24      // 16 h-chunks (K=512) + 8 x-chunks (K=256)

// one K32 chunk of 3-pass split-fp16 mma, warp tile 64x64
__device__ __forceinline__ void compute_chunk(float C[4][8][4], uint32_t st,
                                              uint32_t a_off, uint32_t b_off) {
    #pragma unroll
    for (int kk = 0; kk < 2; kk++) {
        uint32_t Ah[4][4], Bh[4][4];
        #pragma unroll
        for (int mf = 0; mf < 4; mf++) ldsm4(Ah[mf], st + mf * 1280 + kk * 32 + a_off);
        #pragma unroll
        for (int nq = 0; nq < 4; nq++) ldsm4(Bh[nq], st + B_HI + nq * 1280 + kk * 32 + b_off);
        #pragma unroll
        for (int mf = 0; mf < 4; mf++)
            #pragma unroll
            for (int nf = 0; nf < 8; nf++)
                mma16816(C[mf][nf], Ah[mf], &Bh[nf >> 1][(nf & 1) * 2]);
        uint32_t Al[4][4];
        #pragma unroll
        for (int mf = 0; mf < 4; mf++) ldsm4(Al[mf], st + A_LO + mf * 1280 + kk * 32 + a_off);
        #pragma unroll
        for (int mf = 0; mf < 4; mf++)
            #pragma unroll
            for (int nf = 0; nf < 8; nf++)
                mma16816(C[mf][nf], Al[mf], &Bh[nf >> 1][(nf & 1) * 2]);
        uint32_t Bl[4][4];
        #pragma unroll
        for (int nq = 0; nq < 4; nq++) ldsm4(Bl[nq], st + B_HI + B_PL + nq * 1280 + kk * 32 + b_off);
        #pragma unroll
        for (int mf = 0; mf < 4; mf++)
            #pragma unroll
            for (int nf = 0; nf < 8; nf++)
                mma16816(C[mf][nf], Ah[mf], &Bl[nf >> 1][(nf & 1) * 2]);
    }
}

// ---------------- small kernels ----------------
__global__ void k_len(const int* __restrict__ docs) {
    int n = blockIdx.x * blockDim.x + threadIdx.x;
    if (n >= NS) return;
    int cnt = 0;
    #pragma unroll
    for (int t = 0; t < SEQ; t++) cnt += (docs[n * SEQ + t] != 0);
    g_len[n] = cnt;
}
__global__ void k_zero() {
    int idx = blockIdx.x * blockDim.x + threadIdx.x;   // 1048576
    g_c[idx] = 0.f; g_pool[idx] = 0.f;
    g_h16[0][0][idx] = __float2half(0.f);
    g_h16[0][1][idx] = __float2half(0.f);
}
__global__ void k_prep_emb(const float* __restrict__ emb) {
    int idx = blockIdx.x * blockDim.x + threadIdx.x;   // 2048000
    float4 v = ((const float4*)emb)[idx];
    uint32_t h0, l0, h1, l1;
    split2(v.x, v.y, h0, l0); split2(v.z, v.w, h1, l1);
    ((uint2*)g_emb_h)[idx] = make_uint2(h0, h1);
    ((uint2*)g_emb_l)[idx] = make_uint2(l0, l1);
}
__global__ void k_prep_hh(const float* __restrict__ wf, const float* __restrict__ wb) {
    int idx = blockIdx.x * blockDim.x + threadIdx.x;   // 524288
    int k4 = idx & 127, p = (idx >> 7) & 2047, dir = idx >> 18;
    const float* W = dir ? wb : wf;
    float4 v = *(const float4*)(W + (size_t)((p & 3) * HDIM + (p >> 2)) * HDIM + k4 * 4);
    uint32_t h0, l0, h1, l1;
    split2(v.x, v.y, h0, l0); split2(v.z, v.w, h1, l1);
    size_t off = (size_t)(dir * GDIM + p) * HDIM + k4 * 4;
    *(uint2*)(g_whh_h + off) = make_uint2(h0, h1);
    *(uint2*)(g_whh_l + off) = make_uint2(l0, l1);
}
__global__ void k_prep_ih(const float* __restrict__ wf, const float* __restrict__ wb) {
    int idx = blockIdx.x * blockDim.x + threadIdx.x;   // 262144
    int k4 = idx & 63, p = (idx >> 6) & 2047, dir = idx >> 17;
    const float* W = dir ? wb : wf;
    float4 v = *(const float4*)(W + (size_t)((p & 3) * HDIM + (p >> 2)) * EDIM + k4 * 4);
    uint32_t h0, l0, h1, l1;
    split2(v.x, v.y, h0, l0); split2(v.z, v.w, h1, l1);
    size_t off = (size_t)(dir * GDIM + p) * EDIM + k4 * 4;
    *(uint2*)(g_wih_h + off) = make_uint2(h0, h1);
    *(uint2*)(g_wih_l + off) = make_uint2(l0, l1);
}

// ---------------- fused recurrent step ----------------
// CTA: M=128 (n), N=256 (permuted gates p=4j+g), K=768 (512 h + 256 x); grid (8,8,2)
__global__ void __launch_bounds__(256, 1) k_step(
    const int* __restrict__ docs, const float* __restrict__ b_f,
    const float* __restrict__ b_b, int step)
{
    extern __shared__ char smem[];
    const uint32_t sb = smem_u32(smem);
    const int tid = threadIdx.x;
    const int dir = blockIdx.z;
    const int n0  = blockIdx.y * 128;
    const int p0  = blockIdx.x * 256;
    const int u   = dir ? (SEQ - 1 - step) : step;

    int*   tokS  = (int*)(smem + SM_TOK);
    float* biasS = (float*)(smem + SM_BIAS);
    int*   lenS  = (int*)(smem + SM_LEN);

    const __half* __restrict__ H0 = g_h16[step & 1][0] + (size_t)dir * NS * HDIM + (size_t)n0 * HDIM;
    const __half* __restrict__ H1 = g_h16[step & 1][1] + (size_t)dir * NS * HDIM + (size_t)n0 * HDIM;
    const __half* __restrict__ WHH_H = g_whh_h + (size_t)(dir * GDIM + p0) * HDIM;
    const __half* __restrict__ WHH_L = g_whh_l + (size_t)(dir * GDIM + p0) * HDIM;
    const __half* __restrict__ WIH_H = g_wih_h + (size_t)(dir * GDIM + p0) * EDIM;
    const __half* __restrict__ WIH_L = g_wih_l + (size_t)(dir * GDIM + p0) * EDIM;
    const float*  __restrict__ bias  = dir ? b_b : b_f;

    if (tid < 128) {
        tokS[tid] = docs[(n0 + tid) * SEQ + u];
        lenS[tid] = g_len[n0 + tid];
    }
    { int p = p0 + tid; biasS[tid] = bias[(p & 3) * HDIM + (p >> 2)]; }
    __syncthreads();

    const int lane = tid & 31, w = tid >> 5;
    const int mw = w & 1, nw = w >> 1;
    const uint32_t a_off = (mw * 64 + (lane & 15)) * 80 + (lane >> 4) * 16;
    const uint32_t b_off = (nw * 64 + (lane & 7) + ((lane >> 4) << 3)) * 80 + ((lane >> 3) & 1) * 16;

    float bias0[8], bias1[8];
    const int qr = lane >> 2, c2 = (lane & 3) * 2, odd = lane & 1;
    #pragma unroll
    for (int nf = 0; nf < 8; nf++) {
        int pc = nw * 64 + nf * 8 + c2;
        bias0[nf] = biasS[pc];
        bias1[nf] = biasS[pc + 1];
    }

    float C[4][8][4];
    #pragma unroll
    for (int a = 0; a < 4; a++)
        #pragma unroll
        for (int b = 0; b < 8; b++)
            #pragma unroll
            for (int q = 0; q < 4; q++) C[a][b][q] = 0.f;

    auto fill = [&](int ch) {
        uint32_t base = sb + (ch % 3) * ST_SZ;
        if (ch < 16) {
            const int k0 = ch * 32;
            #pragma unroll
            for (int i = 0; i < 4; i++) {
                int s = tid + i * 256;
                int pl = s >> 9, rem = s & 511, r = rem >> 2, kc = rem & 3;
                const __half* src = (pl ? H1 : H0) + r * HDIM + k0 + kc * 8;
                CP_ASYNC16(base + pl * A_LO + r * 80 + kc * 16, src);
            }
            #pragma unroll
            for (int i = 0; i < 8; i++) {
                int s = tid + i * 256;
                int pl = s >> 10, rem = s & 1023, row = rem >> 2, kc = rem & 3;
                const __half* src = (pl ? WHH_L : WHH_H) + (size_t)row * HDIM + k0 + kc * 8;
                CP_ASYNC16(base + B_HI + pl * B_PL + row * 80 + kc * 16, src);
            }
        } else {
            const int k0 = (ch - 16) * 32;
            #pragma unroll
            for (int i = 0; i < 4; i++) {
                int s = tid + i * 256;
                int pl = s >> 9, rem = s & 511, r = rem >> 2, kc = rem & 3;
                const __half* src = (pl ? g_emb_l : g_emb_h) + (size_t)tokS[r] * EDIM + k0 + kc * 8;
                CP_ASYNC16(base + pl * A_LO + r * 80 + kc * 16, src);
            }
            #pragma unroll
            for (int i = 0; i < 8; i++) {
                int s = tid + i * 256;
                int pl = s >> 10, rem = s & 1023, row = rem >> 2, kc = rem & 3;
                const __half* src = (pl ? WIH_L : WIH_H) + (size_t)row * EDIM + k0 + kc * 8;
                CP_ASYNC16(base + B_HI + pl * B_PL + row * 80 + kc * 16, src);
            }
        }
    };

    fill(0); CP_COMMIT();
    fill(1); CP_COMMIT();
    #pragma unroll 1
    for (int ch = 0; ch < NCH; ch++) {
        if (ch + 2 < NCH) { fill(ch + 2); CP_COMMIT(); CP_WAIT(2); }
        else if (ch + 1 < NCH) { CP_WAIT(1); }
        else { CP_WAIT(0); }
        __syncthreads();
        compute_chunk(C, sb + (ch % 3) * ST_SZ, a_off, b_off);
        __syncthreads();
    }

    // ---------------- epilogue (smem-staged, coalesced) ----------------
    float*  cS  = (float*)smem;                 // [128][68]
    float*  pS  = (float*)(smem + 34816);       // [128][68]
    __half* hiS = (__half*)(smem + 69632);      // [128][72]
    __half* loS = (__half*)(smem + 88064);      // [128][72]
    float* __restrict__ gc = g_c    + (size_t)dir * NS * HDIM;
    float* __restrict__ gp = g_pool + (size_t)dir * NS * HDIM;
    const int j0 = p0 >> 2;

    #pragma unroll
    for (int i = 0; i < 8; i++) {               // phase 1: coalesced load c/pool tiles
        int idx = tid + i * 256;
        int r = idx >> 4, q = idx & 15;
        *(float4*)&cS[r * 68 + q * 4] = *(const float4*)&gc[(size_t)(n0 + r) * HDIM + j0 + q * 4];
        *(float4*)&pS[r * 68 + q * 4] = *(const float4*)&gp[(size_t)(n0 + r) * HDIM + j0 + q * 4];
    }
    __syncthreads();

    #pragma unroll
    for (int mf = 0; mf < 4; mf++) {            // phase 2: cell update
        #pragma unroll
        for (int rh = 0; rh < 2; rh++) {
            const int rl = mw * 64 + mf * 16 + qr + rh * 8;
            const bool inlen = (u < lenS[rl]);
            #pragma unroll
            for (int nf = 0; nf < 8; nf++) {
                float y0 = C[mf][nf][rh * 2 + 0] + bias0[nf];
                float y1 = C[mf][nf][rh * 2 + 1] + bias1[nf];
                float o0 = __shfl_xor_sync(0xffffffffu, y0, 1);
                float o1 = __shfl_xor_sync(0xffffffffu, y1, 1);
                if (!odd) {
                    float si = 1.f / (1.f + expf(-y0));
                    float sf = 1.f / (1.f + expf(-y1));
                    float tg = tanhf(o0);
                    float so = 1.f / (1.f + expf(-o1));
                    int jl = (nw * 64 + nf * 8 + c2) >> 2;
                    float c = sf * cS[rl * 68 + jl] + si * tg;
                    float h = so * tanhf(c);
                    cS[rl * 68 + jl] = c;
                    if (inlen) pS[rl * 68 + jl] += h;
                    __half hh = __float2half_rn(h);
                    hiS[rl * 72 + jl] = hh;
                    loS[rl * 72 + jl] = __float2half_rn(h - __half2float(hh));
                }
            }
        }
    }
    __syncthreads();

    __half* __restrict__ NH0 = g_h16[(step + 1) & 1][0] + (size_t)dir * NS * HDIM;
    __half* __restrict__ NH1 = g_h16[(step + 1) & 1][1] + (size_t)dir * NS * HDIM;
    #pragma unroll
    for (int i = 0; i < 8; i++) {               // phase 3: coalesced stores
        int idx = tid + i * 256;
        int r = idx >> 4, q = idx & 15;
        *(float4*)&gc[(size_t)(n0 + r) * HDIM + j0 + q * 4] = *(float4*)&cS[r * 68 + q * 4];
        *(float4*)&gp[(size_t)(n0 + r) * HDIM + j0 + q * 4] = *(float4*)&pS[r * 68 + q * 4];
    }
    #pragma unroll
    for (int i = 0; i < 4; i++) {
        int idx = tid + i * 256;
        int r = idx >> 3, q = idx & 7;
        *(uint4*)&NH0[(size_t)(n0 + r) * HDIM + j0 + q * 8] = *(uint4*)&hiS[r * 72 + q * 8];
        *(uint4*)&NH1[(size_t)(n0 + r) * HDIM + j0 + q * 8] = *(uint4*)&loS[r * 72 + q * 8];
    }
}

// ---------------- final: pool/len, doc mask ----------------
__global__ void k_final(const int* __restrict__ doc_lens, float* __restrict__ out) {
    int idx = blockIdx.x * blockDim.x + threadIdx.x;  // 1048576
    int j  = idx & 1023;
    int nd = idx >> 10;
    int b = nd >> 5, d = nd & 31;
    float v = 0.f;
    if (d < doc_lens[b]) {
        int dirn = j >> 9;
        int jj   = j & 511;
        int len = g_len[nd];
        float denom = (float)(len > 0 ? len : 1);
        v = g_pool[dirn * NS * HDIM + nd * HDIM + jj] / denom;
    }
    out[idx] = v;
}

extern "C" void kernel_launch(void* const* d_in, const int* in_sizes, int n_in,
                              void* d_out, int out_size)
{
    const int* docs     = (const int*)d_in[0];
    const int* doc_lens = (const int*)d_in[1];
    int base = (n_in >= 10 && in_sizes[2] == 1) ? 3 : 2;
    const float* emb   = (const float*)d_in[base + 0];
    const float* wih_f = (const float*)d_in[base + 1];
    const float* whh_f = (const float*)d_in[base + 2];
    const float* b_f   = (const float*)d_in[base + 3];
    const float* wih_b = (const float*)d_in[base + 4];
    const float* whh_b = (const float*)d_in[base + 5];
    const float* b_b   = (const float*)d_in[base + 6];
    float* out = (float*)d_out;

    cudaFuncSetAttribute(k_step, cudaFuncAttributeMaxDynamicSharedMemorySize, SMEM_SZ);

    k_len     <<<4, 256>>>(docs);
    k_zero    <<<4096, 256>>>();
    k_prep_emb<<<8000, 256>>>(emb);
    k_prep_ih <<<1024, 256>>>(wih_f, wih_b);
    k_prep_hh <<<2048, 256>>>(whh_f, whh_b);
    for (int t = 0; t < SEQ; t++)
        k_step<<<dim3(8, 8, 2), 256, SMEM_SZ>>>(docs, b_f, b_b, t);
    k_final   <<<4096, 256>>>(doc_lens, out);
}